// round 16
// baseline (speedup 1.0000x reference)
#include <cuda_runtime.h>
#include <cuda_fp16.h>
#include <cstdint>

// ---------------- scratch (static device globals; no allocation) ----------------
__device__ __half g_Qh[128 * 8 * 128 * 64];   // (bs,H,nq,hd)  16 MB
__device__ __half g_Kh[128 * 8 * 512 * 64];   // (bs,H,ne,hd)  64 MB
__device__ __half g_Vh[128 * 8 * 512 * 64];   // (bs,H,ne,hd)  64 MB
__device__ __half g_Eh[65536 * 512];          // entities fp16  64 MB
__device__ __half g_Wih[1536 * 512];          // W_in fp16
__device__ __half g_Woh[512 * 512];           // W_out fp16
__device__ __half g_Atth[16384 * 512];        // attn out fp16  16 MB
__device__ int    g_mask_kind;                // 0=int32, 1=uint8, 2=float32

// ---------------- mask dtype handling ----------------
__device__ __forceinline__ bool mask_true(const void* p, size_t i, int kind) {
    if (kind == 1) return ((const unsigned char*)p)[i] != 0;
    if (kind == 0) return ((const int*)p)[i] != 0;
    return ((const float*)p)[i] != 0.0f;
}

__global__ void detect_mask_kernel(const unsigned int* __restrict__ pm) {
    if (threadIdx.x == 0) {
        bool is_i32 = true, is_f32 = true;
        for (int i = 0; i < 64; i++) {
            unsigned int w = pm[i];
            if (w != 0u && w != 1u) is_i32 = false;
            if (w != 0u && w != 0x3F800000u) is_f32 = false;
        }
        g_mask_kind = is_i32 ? 0 : (is_f32 ? 2 : 1);
    }
}

// ---------------- fp16 helpers ----------------
__device__ __forceinline__ uint32_t pack2(float a, float b) {
    uint32_t r;
    asm("cvt.rn.f16x2.f32 %0, %1, %2;" : "=r"(r) : "f"(b), "f"(a));
    return r;
}

__device__ __forceinline__ void mma_f16(float* c, uint32_t a0, uint32_t a1,
                                        uint32_t a2, uint32_t a3,
                                        uint32_t b0, uint32_t b1) {
    asm volatile(
        "mma.sync.aligned.m16n8k16.row.col.f32.f16.f16.f32 "
        "{%0,%1,%2,%3}, {%4,%5,%6,%7}, {%8,%9}, {%0,%1,%2,%3};"
        : "+f"(c[0]), "+f"(c[1]), "+f"(c[2]), "+f"(c[3])
        : "r"(a0), "r"(a1), "r"(a2), "r"(a3), "r"(b0), "r"(b1));
}

__device__ __forceinline__ void cp16(uint32_t smem_dst, const void* gsrc) {
    asm volatile("cp.async.ca.shared.global [%0], [%1], 16;" :: "r"(smem_dst), "l"(gsrc));
}

// ---------------- pre-pass: fp32 -> fp16 conversion ----------------
#define NE_ELEMS (65536 * 512)
#define WI_ELEMS (1536 * 512)
#define WO_ELEMS (512 * 512)
#define CVT_BLOCKS ((NE_ELEMS + WI_ELEMS + WO_ELEMS) / 8 / 256)

__global__ __launch_bounds__(256) void convert_fp16(const float* __restrict__ ent,
                                                    const float* __restrict__ wi,
                                                    const float* __restrict__ wo) {
    const size_t i = ((size_t)blockIdx.x * 256 + threadIdx.x) * 8;
    const float* src;
    __half* dst;
    if (i < NE_ELEMS)                   { src = ent + i;                        dst = g_Eh  + i; }
    else if (i < NE_ELEMS + WI_ELEMS)   { src = wi + (i - NE_ELEMS);            dst = g_Wih + (i - NE_ELEMS); }
    else                                { src = wo + (i - NE_ELEMS - WI_ELEMS); dst = g_Woh + (i - NE_ELEMS - WI_ELEMS); }
    const float4 f0 = *(const float4*)src;
    const float4 f1 = *(const float4*)(src + 4);
    uint4 u;
    u.x = pack2(f0.x, f0.y); u.y = pack2(f0.z, f0.w);
    u.z = pack2(f1.x, f1.y); u.w = pack2(f1.z, f1.w);
    *(uint4*)dst = u;
}

// ---------------- async fp16 GEMM: ring-of-6 k16 buffers, barrier per k32 ----------------
// smem (dynamic): 6 bufs x (A,B) x [128 rows x 12 words]  = 73728 B
// 32 k16 stages total (K=512); 16 groups of 2 stages; one barrier per group.
#define GEMM_SMEM_BYTES (6 * 2 * 1536 * 4)

#define GEMM_FRAG_COMPUTE(Ab, Bb)                                              \
    do {                                                                       \
        uint32_t a0[2], a1[2], a2[2], a3[2];                                   \
        _Pragma("unroll")                                                      \
        for (int mt = 0; mt < 2; mt++) {                                       \
            const uint32_t* ap = (Ab) + (wm + (mt << 4) + g) * 12 + t;         \
            a0[mt] = ap[0];  a2[mt] = ap[4];                                   \
            a1[mt] = ap[96]; a3[mt] = ap[100];                                 \
        }                                                                      \
        _Pragma("unroll")                                                      \
        for (int nt = 0; nt < 8; nt++) {                                       \
            const uint32_t* bp = (Bb) + (wn + (nt << 3) + g) * 12 + t;         \
            const uint32_t b0 = bp[0], b1 = bp[4];                             \
            mma_f16(c[0][nt], a0[0], a1[0], a2[0], a3[0], b0, b1);             \
            mma_f16(c[1][nt], a0[1], a1[1], a2[1], a3[1], b0, b1);             \
        }                                                                      \
    } while (0)

// Fused QKV projection:
//   blocks y <  512 : KV mode  C[65536][1024] -> g_Kh/g_Vh (fp16)
//   blocks y >= 512 : Q  mode  C[16384][512] (A rows b*512+q) -> g_Qh (x0.125, fp16)
__global__ __launch_bounds__(256, 2) void qkv_fused(int dummy) {
    extern __shared__ uint32_t Sw[];

    const int tid  = threadIdx.x;
    const int lane = tid & 31;
    const int wid  = tid >> 5;
    const int g    = lane >> 2;
    const int t    = lane & 3;
    const int wm   = (wid >> 1) << 5;
    const int wn   = (wid & 1) << 6;

    const bool qm = (blockIdx.y >= 512);
    int bm, bn;
    size_t woff;
    if (!qm) {
        bm = blockIdx.y << 7;
        bn = blockIdx.x << 7;
        woff = (size_t)512 * 512;
    } else {
        const int idx = ((blockIdx.y - 512) << 3) + blockIdx.x;   // 0..511
        bm = (idx >> 2) << 7;
        bn = (idx & 3) << 7;
        woff = 0;
    }

    const int r = tid >> 1;
    const int h = tid & 1;
    int arow = bm + r;
    if (qm) arow = ((arow >> 7) << 9) | (arow & 127);     // b*512 + q
    const __half* Ag = g_Eh + (size_t)arow * 512 + (h << 3);
    const __half* Wg = g_Wih + woff + (size_t)(bn + r) * 512 + (h << 3);
    const uint32_t sb = (uint32_t)__cvta_generic_to_shared(Sw) + (uint32_t)((r * 12 + h * 4) << 2);

#define QKV_ISSUE(s, buf)                        \
    do {                                         \
        cp16(sb + (buf) * 12288, Ag + (s) * 16); \
        cp16(sb + (buf) * 12288 + 6144, Wg + (s) * 16); \
    } while (0)

    // prologue: stages 0..3 (groups 0,1)
    QKV_ISSUE(0, 0); QKV_ISSUE(1, 1);
    asm volatile("cp.async.commit_group;");
    QKV_ISSUE(2, 2); QKV_ISSUE(3, 3);
    asm volatile("cp.async.commit_group;");

    float c[2][8][4];
#pragma unroll
    for (int mt = 0; mt < 2; mt++)
#pragma unroll
        for (int nt = 0; nt < 8; nt++)
#pragma unroll
            for (int i = 0; i < 4; i++) c[mt][nt][i] = 0.f;

    int b0 = 0;   // buffer of stage 2*gi
    for (int gi = 0; gi < 16; gi++) {
        asm volatile("cp.async.wait_group 1;");
        __syncthreads();
        if (gi < 14) {
            const int s0 = 2 * gi + 4;
            int nb0 = b0 + 4; if (nb0 >= 6) nb0 -= 6;
            int nb1 = nb0 + 1; if (nb1 >= 6) nb1 -= 6;
            QKV_ISSUE(s0, nb0);
            QKV_ISSUE(s0 + 1, nb1);
        }
        asm volatile("cp.async.commit_group;");

        {
            const uint32_t* Ab = Sw + b0 * 3072;
            GEMM_FRAG_COMPUTE(Ab, Ab + 1536);
        }
        {
            int b1 = b0 + 1; if (b1 >= 6) b1 -= 6;
            const uint32_t* Ab = Sw + b1 * 3072;
            GEMM_FRAG_COMPUTE(Ab, Ab + 1536);
        }
        b0 += 2; if (b0 >= 6) b0 -= 6;
    }

    if (qm) {
        const int hh = (bn + wn) >> 6;
        uint32_t* Qw = (uint32_t*)g_Qh;
#pragma unroll
        for (int mt = 0; mt < 2; mt++) {
            const int m0 = bm + wm + (mt << 4) + g;
            const int m1 = m0 + 8;
            const size_t i0 = (size_t)(((((m0 >> 7) << 3) + hh) << 7) + (m0 & 127)) * 64;
            const size_t i1 = (size_t)(((((m1 >> 7) << 3) + hh) << 7) + (m1 & 127)) * 64;
#pragma unroll
            for (int nt = 0; nt < 8; nt++) {
                const int d = (nt << 3) + (t << 1);
                Qw[(i0 + d) >> 1] = pack2(c[mt][nt][0] * 0.125f, c[mt][nt][1] * 0.125f);
                Qw[(i1 + d) >> 1] = pack2(c[mt][nt][2] * 0.125f, c[mt][nt][3] * 0.125f);
            }
        }
    } else {
        uint32_t* basew = (uint32_t*)((bn >= 512) ? g_Vh : g_Kh);
        const int hh = ((bn + wn) >> 6) & 7;
#pragma unroll
        for (int mt = 0; mt < 2; mt++) {
            const int m0 = bm + wm + (mt << 4) + g;
            const int m1 = m0 + 8;
            const size_t i0 = (size_t)(((((m0 >> 9) << 3) + hh) << 9) + (m0 & 511)) * 64;
            const size_t i1 = (size_t)(((((m1 >> 9) << 3) + hh) << 9) + (m1 & 511)) * 64;
#pragma unroll
            for (int nt = 0; nt < 8; nt++) {
                const int d = (nt << 3) + (t << 1);
                basew[(i0 + d) >> 1] = pack2(c[mt][nt][0], c[mt][nt][1]);
                basew[(i1 + d) >> 1] = pack2(c[mt][nt][2], c[mt][nt][3]);
            }
        }
    }
    (void)dummy;
}

// Output projection: C = g_Atth[16384][512] @ g_Woh[512][512]^T + bias, post-mask
__global__ __launch_bounds__(256, 2) void out_gemm(const float* __restrict__ bias,
                                                   const void* __restrict__ post_mask,
                                                   float* __restrict__ out) {
    extern __shared__ uint32_t Sw[];

    const int tid  = threadIdx.x;
    const int lane = tid & 31;
    const int wid  = tid >> 5;
    const int g    = lane >> 2;
    const int t    = lane & 3;
    const int wm   = (wid >> 1) << 5;
    const int wn   = (wid & 1) << 6;
    const int bm   = blockIdx.y << 7;
    const int bn   = blockIdx.x << 7;

    const int r = tid >> 1;
    const int h = tid & 1;
    const __half* Ag = g_Atth + (size_t)(bm + r) * 512 + (h << 3);
    const __half* Wg = g_Woh + (size_t)(bn + r) * 512 + (h << 3);
    const uint32_t sb = (uint32_t)__cvta_generic_to_shared(Sw) + (uint32_t)((r * 12 + h * 4) << 2);

#define OUT_ISSUE(s, buf)                        \
    do {                                         \
        cp16(sb + (buf) * 12288, Ag + (s) * 16); \
        cp16(sb + (buf) * 12288 + 6144, Wg + (s) * 16); \
    } while (0)

    OUT_ISSUE(0, 0); OUT_ISSUE(1, 1);
    asm volatile("cp.async.commit_group;");
    OUT_ISSUE(2, 2); OUT_ISSUE(3, 3);
    asm volatile("cp.async.commit_group;");

    float c[2][8][4];
#pragma unroll
    for (int mt = 0; mt < 2; mt++)
#pragma unroll
        for (int nt = 0; nt < 8; nt++)
#pragma unroll
            for (int i = 0; i < 4; i++) c[mt][nt][i] = 0.f;

    int b0 = 0;
    for (int gi = 0; gi < 16; gi++) {
        asm volatile("cp.async.wait_group 1;");
        __syncthreads();
        if (gi < 14) {
            const int s0 = 2 * gi + 4;
            int nb0 = b0 + 4; if (nb0 >= 6) nb0 -= 6;
            int nb1 = nb0 + 1; if (nb1 >= 6) nb1 -= 6;
            OUT_ISSUE(s0, nb0);
            OUT_ISSUE(s0 + 1, nb1);
        }
        asm volatile("cp.async.commit_group;");

        {
            const uint32_t* Ab = Sw + b0 * 3072;
            GEMM_FRAG_COMPUTE(Ab, Ab + 1536);
        }
        {
            int b1 = b0 + 1; if (b1 >= 6) b1 -= 6;
            const uint32_t* Ab = Sw + b1 * 3072;
            GEMM_FRAG_COMPUTE(Ab, Ab + 1536);
        }
        b0 += 2; if (b0 >= 6) b0 -= 6;
    }

    const int kind = g_mask_kind;
#pragma unroll
    for (int mt = 0; mt < 2; mt++) {
        const int m0 = bm + wm + (mt << 4) + g;
        const int m1 = m0 + 8;
        const bool pm0 = mask_true(post_mask, m0, kind);
        const bool pm1 = mask_true(post_mask, m1, kind);
        float* p0 = out + (size_t)m0 * 512 + bn + wn;
        float* p1 = out + (size_t)m1 * 512 + bn + wn;
#pragma unroll
        for (int nt = 0; nt < 8; nt++) {
            const int d = (nt << 3) + (t << 1);
            const float2 bb = *(const float2*)&bias[bn + wn + d];
            *(float2*)(p0 + d) = pm0 ? make_float2(0.f, 0.f)
                                     : make_float2(c[mt][nt][0] + bb.x, c[mt][nt][1] + bb.y);
            *(float2*)(p1 + d) = pm1 ? make_float2(0.f, 0.f)
                                     : make_float2(c[mt][nt][2] + bb.x, c[mt][nt][3] + bb.y);
        }
    }
}

// ---------------- K2: fp16 flash attention, 128 threads / 64 queries per CTA ----------------
// smem (words): Qs [64][36] 2304 | stats [4][32][4] 512 | KVbuf [2][K,V][128][36] 18432
#define AQ_W   0
#define AST_W  2304
#define AKV_W  2816
#define ATT_SMEM_WORDS (2816 + 4 * 4608)
#define ATT_SMEM_BYTES (ATT_SMEM_WORDS * 4)

__global__ __launch_bounds__(128, 2) void attn_kernel(const void* __restrict__ pre_mask,
                                                      const float* __restrict__ diff_mask) {
    extern __shared__ uint32_t smw[];
    uint32_t* Qs    = smw + AQ_W;
    float*    stats = (float*)(smw + AST_W);
    uint32_t* KVbuf = smw + AKV_W;

    const int tid  = threadIdx.x;
    const int lane = tid & 31;
    const int w    = tid >> 5;          // warp 0..3
    const int g    = lane >> 2;
    const int t    = lane & 3;
    const int wm   = (w >> 1) << 5;     // local query offset 0/32
    const int wn   = (w & 1) << 6;      // key offset within tile 0/64

    const int head = blockIdx.x;
    const int b    = blockIdx.y >> 1;
    const int qbase = (blockIdx.y & 1) << 6;
    const int bh = (b << 3) + head;
    const __half* Qg = g_Qh + ((size_t)bh * 128 + qbase) * 64;
    const __half* Kg = g_Kh + (size_t)bh * 512 * 64;
    const __half* Vg = g_Vh + (size_t)bh * 512 * 64;
    const int kind = g_mask_kind;
    const size_t qrow0 = (size_t)b * 128 + qbase;
    const float NEG_INF = __int_as_float(0xff800000u);

    uint32_t bufa[4];
#pragma unroll
    for (int i = 0; i < 4; i++)
        bufa[i] = (uint32_t)__cvta_generic_to_shared(KVbuf + i * 4608);

    // ---- prologue: tile 0 K/V ----
#pragma unroll
    for (int i = 0; i < 8; i++) {
        const int idx = (i << 7) + tid;           // 0..1023
        const int key = idx >> 3, ch = idx & 7;
        const int dw = (key * 36 + (ch << 2)) << 2;
        cp16(bufa[0] + dw, Kg + (key << 6) + (ch << 3));
        cp16(bufa[1] + dw, Vg + (key << 6) + (ch << 3));
    }
    asm volatile("cp.async.commit_group;");

    // ---- stage Q (64 rows) ----
#pragma unroll
    for (int i = 0; i < 4; i++) {
        const int idx = (i << 7) + tid;           // 0..511
        const int q = idx >> 3, ch = idx & 7;
        const uint4 v = *(const uint4*)(Qg + (q << 6) + (ch << 3));
        *(uint4*)&Qs[q * 36 + (ch << 2)] = v;
    }

    float m[4], E[4], D[4];
#pragma unroll
    for (int r = 0; r < 4; r++) { m[r] = NEG_INF; E[r] = 0.f; D[r] = 0.f; }
    float o[2][8][4];
#pragma unroll
    for (int mt = 0; mt < 2; mt++)
#pragma unroll
        for (int dn = 0; dn < 8; dn++)
#pragma unroll
            for (int i = 0; i < 4; i++) o[mt][dn][i] = 0.f;

    for (int tile = 0; tile < 4; tile++) {
        if (tile < 3) {
            const int nb = (tile + 1) & 1;
            const __half* Kgt = Kg + (size_t)((tile + 1) << 7) * 64;
            const __half* Vgt = Vg + (size_t)((tile + 1) << 7) * 64;
#pragma unroll
            for (int i = 0; i < 8; i++) {
                const int idx = (i << 7) + tid;
                const int key = idx >> 3, ch = idx & 7;
                const int dw = (key * 36 + (ch << 2)) << 2;
                cp16(bufa[nb * 2 + 0] + dw, Kgt + (key << 6) + (ch << 3));
                cp16(bufa[nb * 2 + 1] + dw, Vgt + (key << 6) + (ch << 3));
            }
            asm volatile("cp.async.commit_group;");
            asm volatile("cp.async.wait_group 1;");
        } else {
            asm volatile("cp.async.wait_group 0;");
        }
        __syncthreads();

        const uint32_t* Kb = KVbuf + (size_t)((tile & 1) * 2 + 0) * 4608;
        const uint32_t  Vb_base = bufa[(tile & 1) * 2 + 1]
                                + (((wn + (lane & 15)) * 36 + ((lane & 16) ? 4 : 0)) << 2);

        // ---- preload masks ----
        float2 dmx[4][8];
#pragma unroll
        for (int mt = 0; mt < 2; mt++)
#pragma unroll
            for (int hh = 0; hh < 2; hh++) {
                const int r = mt * 2 + hh;
                const size_t row = qrow0 + wm + (mt << 4) + (hh << 3) + g;
                const size_t base = row * 512 + (tile << 7) + wn + (t << 1);
#pragma unroll
                for (int nt = 0; nt < 8; nt++) {
                    const size_t ix = base + (nt << 3);
                    const float2 d2 = *(const float2*)(diff_mask + ix);
                    bool p0, p1;
                    if (kind == 1) {
                        const uchar2 u = *(const uchar2*)((const unsigned char*)pre_mask + ix);
                        p0 = u.x != 0; p1 = u.y != 0;
                    } else if (kind == 0) {
                        const int2 u = *(const int2*)((const int*)pre_mask + ix);
                        p0 = u.x != 0; p1 = u.y != 0;
                    } else {
                        const float2 u = *(const float2*)((const float*)pre_mask + ix);
                        p0 = u.x != 0.f; p1 = u.y != 0.f;
                    }
                    dmx[r][nt] = make_float2(p0 ? -1.f : d2.x, p1 ? -1.f : d2.y);
                }
            }

        // ---- S = Q @ K^T ----
        float c[2][8][4];
#pragma unroll
        for (int mt = 0; mt < 2; mt++)
#pragma unroll
            for (int nt = 0; nt < 8; nt++)
#pragma unroll
                for (int i = 0; i < 4; i++) c[mt][nt][i] = 0.f;

#pragma unroll
        for (int ks = 0; ks < 4; ks++) {
            uint32_t a0[2], a1[2], a2[2], a3[2];
#pragma unroll
            for (int mt = 0; mt < 2; mt++) {
                const uint32_t* ap = Qs + (wm + (mt << 4) + g) * 36 + (ks << 3) + t;
                a0[mt] = ap[0];
                a2[mt] = ap[4];
                a1[mt] = ap[288];
                a3[mt] = ap[292];
            }
#pragma unroll
            for (int nt = 0; nt < 8; nt++) {
                const uint32_t* bp = Kb + (wn + (nt << 3) + g) * 36 + (ks << 3) + t;
                const uint32_t b0 = bp[0], b1 = bp[4];
                mma_f16(c[0][nt], a0[0], a1[0], a2[0], a3[0], b0, b1);
                mma_f16(c[1][nt], a0[1], a1[1], a2[1], a3[1], b0, b1);
            }
        }

        // ---- online softmax update ----
#pragma unroll
        for (int mt = 0; mt < 2; mt++)
#pragma unroll
            for (int hh = 0; hh < 2; hh++) {
                const int r = mt * 2 + hh;
                const int s0i = hh * 2, s1i = hh * 2 + 1;
                float tmax = NEG_INF;
#pragma unroll
                for (int nt = 0; nt < 8; nt++) {
                    const float2 dmv = dmx[r][nt];
                    float s0 = (dmv.x < 0.f) ? NEG_INF : c[mt][nt][s0i];
                    float s1 = (dmv.y < 0.f) ? NEG_INF : c[mt][nt][s1i];
                    c[mt][nt][s0i] = s0; c[mt][nt][s1i] = s1;
                    tmax = fmaxf(tmax, fmaxf(s0, s1));
                }
                tmax = fmaxf(tmax, __shfl_xor_sync(0xffffffffu, tmax, 1));
                tmax = fmaxf(tmax, __shfl_xor_sync(0xffffffffu, tmax, 2));
                const float mnew = fmaxf(m[r], tmax);
                const float sc = (m[r] == NEG_INF) ? 0.f : __expf(m[r] - mnew);
                m[r] = mnew;
                E[r] *= sc; D[r] *= sc;
#pragma unroll
                for (int dn = 0; dn < 8; dn++) { o[mt][dn][s0i] *= sc; o[mt][dn][s1i] *= sc; }
                float eacc = 0.f, dacc = 0.f;
#pragma unroll
                for (int nt = 0; nt < 8; nt++) {
                    const float2 dmv = dmx[r][nt];
                    const float s0 = c[mt][nt][s0i], s1 = c[mt][nt][s1i];
                    const float e0 = (s0 == NEG_INF) ? 0.f : __expf(s0 - mnew);
                    const float e1 = (s1 == NEG_INF) ? 0.f : __expf(s1 - mnew);
                    const float w0 = e0 * dmv.x, w1 = e1 * dmv.y;
                    eacc += e0 + e1; dacc += w0 + w1;
                    c[mt][nt][s0i] = w0; c[mt][nt][s1i] = w1;
                }
                E[r] += eacc; D[r] += dacc;
            }

        // ---- O += wd @ V ----
#pragma unroll
        for (int ks = 0; ks < 4; ks++) {
            uint32_t aa[2][4];
#pragma unroll
            for (int mt = 0; mt < 2; mt++) {
                aa[mt][0] = pack2(c[mt][2 * ks][0],     c[mt][2 * ks][1]);
                aa[mt][1] = pack2(c[mt][2 * ks][2],     c[mt][2 * ks][3]);
                aa[mt][2] = pack2(c[mt][2 * ks + 1][0], c[mt][2 * ks + 1][1]);
                aa[mt][3] = pack2(c[mt][2 * ks + 1][2], c[mt][2 * ks + 1][3]);
            }
#pragma unroll
            for (int dn2 = 0; dn2 < 4; dn2++) {
                uint32_t r0, r1, r2, r3;
                const uint32_t addr = Vb_base + (((ks << 4) * 36 + (dn2 << 3)) << 2);
                asm volatile(
                    "ldmatrix.sync.aligned.m8n8.x4.trans.shared.b16 {%0,%1,%2,%3}, [%4];"
                    : "=r"(r0), "=r"(r1), "=r"(r2), "=r"(r3) : "r"(addr));
                mma_f16(o[0][2 * dn2],     aa[0][0], aa[0][1], aa[0][2], aa[0][3], r0, r1);
                mma_f16(o[0][2 * dn2 + 1], aa[0][0], aa[0][1], aa[0][2], aa[0][3], r2, r3);
                mma_f16(o[1][2 * dn2],     aa[1][0], aa[1][1], aa[1][2], aa[1][3], r0, r1);
                mma_f16(o[1][2 * dn2 + 1], aa[1][0], aa[1][1], aa[1][2], aa[1][3], r2, r3);
            }
        }
        __syncthreads();
    }

    // ---- merge stats across the two warp columns ----
#pragma unroll
    for (int r = 0; r < 4; r++) {
        E[r] += __shfl_xor_sync(0xffffffffu, E[r], 1);
        E[r] += __shfl_xor_sync(0xffffffffu, E[r], 2);
        D[r] += __shfl_xor_sync(0xffffffffu, D[r], 1);
        D[r] += __shfl_xor_sync(0xffffffffu, D[r], 2);
    }
    if (t == 0) {
#pragma unroll
        for (int mt = 0; mt < 2; mt++)
#pragma unroll
            for (int hh = 0; hh < 2; hh++) {
                const int r = mt * 2 + hh;
                float* sp = stats + ((w << 5) + (mt << 4) + (hh << 3) + g) * 4;
                sp[0] = m[r]; sp[1] = E[r]; sp[2] = D[r];
            }
    }
    __syncthreads();

    float fac[4];
#pragma unroll
    for (int mt = 0; mt < 2; mt++)
#pragma unroll
        for (int hh = 0; hh < 2; hh++) {
            const int r = mt * 2 + hh;
            const float* sp = stats + (((w ^ 1) << 5) + (mt << 4) + (hh << 3) + g) * 4;
            const float pm_ = sp[0], pE = sp[1], pD = sp[2];
            const float mt_ = fmaxf(m[r], pm_);
            const float ss = (m[r] == NEG_INF) ? 0.f : __expf(m[r] - mt_);
            const float sq = (pm_ == NEG_INF) ? 0.f : __expf(pm_ - mt_);
            const float Et = ss * E[r] + sq * pE;
            const float Dt = ss * D[r] + sq * pD;
            const float inv = (Et > 0.f) ? 1.f / (Dt + 1e-8f * Et) : 0.f;
            fac[r] = inv * ss;
        }
#pragma unroll
    for (int mt = 0; mt < 2; mt++)
#pragma unroll
        for (int dn = 0; dn < 8; dn++) {
            o[mt][dn][0] *= fac[mt * 2];     o[mt][dn][1] *= fac[mt * 2];
            o[mt][dn][2] *= fac[mt * 2 + 1]; o[mt][dn][3] *= fac[mt * 2 + 1];
        }

    // ---- reduce O across the warp-column pair; write g_Atth (fp16) ----
    float* Ored = (float*)KVbuf;   // [64][68] f32 fits
    if (w & 1) {
#pragma unroll
        for (int mt = 0; mt < 2; mt++) {
            const int q0 = wm + (mt << 4) + g;
#pragma unroll
            for (int dn = 0; dn < 8; dn++) {
                const int d = (dn << 3) + (t << 1);
                *(float2*)&Ored[q0 * 68 + d]       = make_float2(o[mt][dn][0], o[mt][dn][1]);
                *(float2*)&Ored[(q0 + 8) * 68 + d] = make_float2(o[mt][dn][2], o[mt][dn][3]);
            }
        }
    }
    __syncthreads();
    if (!(w & 1)) {
        uint32_t* Ah = (uint32_t*)g_Atth;
#pragma unroll
        for (int mt = 0; mt < 2; mt++) {
            const int q0 = wm + (mt << 4) + g;
#pragma unroll
            for (int dn = 0; dn < 8; dn++) {
                const int d = (dn << 3) + (t << 1);
                const float2 p0 = *(const float2*)&Ored[q0 * 68 + d];
                const float2 p1 = *(const float2*)&Ored[(q0 + 8) * 68 + d];
                const size_t ob = (qrow0 + q0) * 512 + (head << 6) + d;
                Ah[ob >> 1]          = pack2(o[mt][dn][0] + p0.x, o[mt][dn][1] + p0.y);
                Ah[(ob + 4096) >> 1] = pack2(o[mt][dn][2] + p1.x, o[mt][dn][3] + p1.y);
            }
        }
    }
}

// ---------------- launcher ----------------
extern "C" void kernel_launch(void* const* d_in, const int* in_sizes, int n_in,
                              void* d_out, int out_size) {
    (void)in_sizes; (void)n_in; (void)out_size;
    const float* entities  = (const float*)d_in[0];
    const void*  pre_mask  = d_in[1];
    const float* diff_mask = (const float*)d_in[2];
    const void*  post_mask = d_in[3];
    const float* W_in      = (const float*)d_in[4];
    const float* W_out     = (const float*)d_in[5];
    const float* b_out     = (const float*)d_in[6];
    float* out = (float*)d_out;

    cudaFuncSetAttribute(attn_kernel, cudaFuncAttributeMaxDynamicSharedMemorySize,
                         ATT_SMEM_BYTES);
    cudaFuncSetAttribute(qkv_fused, cudaFuncAttributeMaxDynamicSharedMemorySize,
                         GEMM_SMEM_BYTES);
    cudaFuncSetAttribute(out_gemm, cudaFuncAttributeMaxDynamicSharedMemorySize,
                         GEMM_SMEM_BYTES);

    detect_mask_kernel<<<1, 32>>>((const unsigned int*)pre_mask);
    convert_fp16<<<CVT_BLOCKS, 256>>>(entities, W_in, W_out);
    qkv_fused<<<dim3(8, 576), 256, GEMM_SMEM_BYTES>>>(0);                 // Q + K + V
    attn_kernel<<<dim3(8, 256), 128, ATT_SMEM_BYTES>>>(pre_mask, diff_mask);
    out_gemm<<<dim3(4, 128), 256, GEMM_SMEM_BYTES>>>(b_out, post_mask, out);
}